// round 1
// baseline (speedup 1.0000x reference)
#include <cuda_runtime.h>
#include <cuda_fp16.h>
#include <cstdint>
#include <cstddef>

// ---------------- problem constants ----------------
#define TOK 16384     // B*S = 4*4096 tokens
#define HD  2048      // hidden
#define ID  4096      // intermediate = 2*H
#define NG  4         // num grouped gemm groups

// ---------------- device scratch (no allocs allowed -> __device__ globals) ----------------
__device__ __half g_bufA[(size_t)TOK * ID];
__device__ __half g_bufB[(size_t)TOK * ID];
__device__ __half g_w1h [(size_t)ID * HD];
__device__ __half g_w2h [(size_t)HD * ID];
__device__ __half g_l0g1[(size_t)NG * ID * HD];
__device__ __half g_l0g2[(size_t)NG * HD * ID];
__device__ __half g_l1g1[(size_t)NG * ID * HD];
__device__ __half g_l1g2[(size_t)NG * HD * ID];

// ---------------- fp32 -> fp16 conversion ----------------
__global__ void f2h_kernel(const float4* __restrict__ src, __half2* __restrict__ dst, size_t n4) {
    size_t i = (size_t)blockIdx.x * blockDim.x + threadIdx.x;
    if (i < n4) {
        float4 v = src[i];
        dst[2 * i]     = __floats2half2_rn(v.x, v.y);
        dst[2 * i + 1] = __floats2half2_rn(v.z, v.w);
    }
}

// ---------------- GEMM tile config ----------------
constexpr int BM = 128, BN = 128, BK = 64;
constexpr int STAGES = 3;
constexpr int LDS_ = BK + 8;   // 72 halfs per row (144B) -> conflict-free ldmatrix
constexpr int SMEM_BYTES = STAGES * (BM + BN) * LDS_ * 2;

// ---------------- PTX helpers ----------------
__device__ __forceinline__ uint32_t smem_u32(const void* p) {
    return (uint32_t)__cvta_generic_to_shared(p);
}
__device__ __forceinline__ void cp16(const __half* s, const __half* g) {
    asm volatile("cp.async.cg.shared.global [%0], [%1], 16;\n" :: "r"(smem_u32(s)), "l"(g));
}
__device__ __forceinline__ void cp_commit() { asm volatile("cp.async.commit_group;\n"); }
template <int N>
__device__ __forceinline__ void cp_wait() { asm volatile("cp.async.wait_group %0;\n" :: "n"(N)); }

__device__ __forceinline__ void ldsm_x4(uint32_t* r, uint32_t addr) {
    asm volatile("ldmatrix.sync.aligned.m8n8.x4.shared.b16 {%0,%1,%2,%3}, [%4];\n"
                 : "=r"(r[0]), "=r"(r[1]), "=r"(r[2]), "=r"(r[3]) : "r"(addr));
}
__device__ __forceinline__ void mma16816(float* c, const uint32_t* a, const uint32_t* b) {
    asm volatile("mma.sync.aligned.m16n8k16.row.col.f32.f16.f16.f32 "
                 "{%0,%1,%2,%3}, {%4,%5,%6,%7}, {%8,%9}, {%0,%1,%2,%3};\n"
                 : "+f"(c[0]), "+f"(c[1]), "+f"(c[2]), "+f"(c[3])
                 : "r"(a[0]), "r"(a[1]), "r"(a[2]), "r"(a[3]), "r"(b[0]), "r"(b[1]));
}

// ---------------- fp16 GEMM:  C[M,N] = A[M,K] * W[N,K]^T + bias ----------------
// W may be grouped along M: group = bm / mRowsPerGroup, weight block stride N*K, bias stride N.
template <typename OutT>
__global__ __launch_bounds__(256)
void gemm_kernel(const __half* __restrict__ A, const __half* __restrict__ W,
                 const float* __restrict__ bias, OutT* __restrict__ C,
                 int M, int N, int K, int mRowsPerGroup) {
    extern __shared__ char smem_raw[];
    __half* sA = (__half*)smem_raw;
    __half* sB = sA + STAGES * BM * LDS_;

    const int tid  = threadIdx.x;
    const int lane = tid & 31;
    const int warp = tid >> 5;
    const int wm   = warp >> 2;   // 0..1 -> 64 rows each
    const int wn   = warp & 3;    // 0..3 -> 32 cols each
    const int bm   = blockIdx.y * BM;
    const int bn   = blockIdx.x * BN;
    const int group = bm / mRowsPerGroup;

    const __half* gA = A + (size_t)bm * K;
    const __half* gB = W + (size_t)group * N * K + (size_t)bn * K;
    const float*  biasg = bias + (size_t)group * N;
    const int kTiles = K / BK;

    float acc[4][4][4];
#pragma unroll
    for (int a = 0; a < 4; a++)
#pragma unroll
        for (int b = 0; b < 4; b++)
#pragma unroll
            for (int c = 0; c < 4; c++) acc[a][b][c] = 0.f;

    auto load_stage = [&](int stage, int kt) {
        __half* dA = sA + stage * BM * LDS_;
        __half* dB = sB + stage * BN * LDS_;
#pragma unroll
        for (int j = 0; j < 4; j++) {            // 1024 16B chunks / 256 threads
            int chunk = tid + j * 256;
            int row = chunk >> 3, c8 = chunk & 7;
            cp16(dA + row * LDS_ + c8 * 8, gA + (size_t)row * K + (size_t)kt * BK + c8 * 8);
        }
#pragma unroll
        for (int j = 0; j < 4; j++) {
            int chunk = tid + j * 256;
            int row = chunk >> 3, c8 = chunk & 7;
            cp16(dB + row * LDS_ + c8 * 8, gB + (size_t)row * K + (size_t)kt * BK + c8 * 8);
        }
    };

    // prologue: STAGES-1 tiles in flight
    for (int s = 0; s < STAGES - 1; ++s) { load_stage(s, s); cp_commit(); }

    for (int kt = 0; kt < kTiles; ++kt) {
        cp_wait<STAGES - 2>();
        __syncthreads();   // stage kt resident; also protects stage about to be overwritten below

        const __half* cA = sA + (kt % STAGES) * BM * LDS_;
        const __half* cB = sB + (kt % STAGES) * BN * LDS_;

#pragma unroll
        for (int ks = 0; ks < BK / 16; ++ks) {
            uint32_t aF[4][4], bF[4][2];
#pragma unroll
            for (int mi = 0; mi < 4; ++mi) {
                int r = wm * 64 + mi * 16 + (lane & 15);
                int c = ks * 16 + (lane >> 4) * 8;
                ldsm_x4(aF[mi], smem_u32(cA + r * LDS_ + c));
            }
#pragma unroll
            for (int np = 0; np < 2; ++np) {      // loads B frags for ni = 2np, 2np+1
                int r = wn * 32 + np * 16 + ((lane >> 4) & 1) * 8 + (lane & 7);
                int c = ks * 16 + ((lane >> 3) & 1) * 8;
                uint32_t t[4];
                ldsm_x4(t, smem_u32(cB + r * LDS_ + c));
                bF[2 * np][0] = t[0]; bF[2 * np][1] = t[1];
                bF[2 * np + 1][0] = t[2]; bF[2 * np + 1][1] = t[3];
            }
#pragma unroll
            for (int mi = 0; mi < 4; ++mi)
#pragma unroll
                for (int ni = 0; ni < 4; ++ni)
                    mma16816(acc[mi][ni], aF[mi], bF[ni]);
        }

        int nk = kt + STAGES - 1;
        if (nk < kTiles) load_stage(nk % STAGES, nk);
        cp_commit();   // commit (possibly empty) keeps group accounting uniform
    }

    // ---------------- epilogue: bias add + store ----------------
#pragma unroll
    for (int mi = 0; mi < 4; ++mi) {
#pragma unroll
        for (int ni = 0; ni < 4; ++ni) {
            int r0 = bm + wm * 64 + mi * 16 + (lane >> 2);
            int c0 = bn + wn * 32 + ni * 8 + (lane & 3) * 2;
            float bv0 = biasg[c0], bv1 = biasg[c0 + 1];
            float v0 = acc[mi][ni][0] + bv0;
            float v1 = acc[mi][ni][1] + bv1;
            float v2 = acc[mi][ni][2] + bv0;
            float v3 = acc[mi][ni][3] + bv1;
            if constexpr (sizeof(OutT) == 2) {
                *(__half2*)((__half*)C + (size_t)r0 * N + c0)       = __floats2half2_rn(v0, v1);
                *(__half2*)((__half*)C + (size_t)(r0 + 8) * N + c0) = __floats2half2_rn(v2, v3);
            } else {
                *(float2*)((float*)C + (size_t)r0 * N + c0)       = make_float2(v0, v1);
                *(float2*)((float*)C + (size_t)(r0 + 8) * N + c0) = make_float2(v2, v3);
            }
        }
    }
}

// ---------------- host launcher ----------------
static inline void* sym_addr(const void* symbol) {
    void* p = nullptr;
    cudaGetSymbolAddress(&p, symbol);
    return p;
}

extern "C" void kernel_launch(void* const* d_in, const int* in_sizes, int n_in,
                              void* d_out, int out_size) {
    const float* x    = (const float*)d_in[0];
    const float* w1   = (const float*)d_in[1];
    const float* b1   = (const float*)d_in[2];
    const float* w2   = (const float*)d_in[3];
    const float* b2   = (const float*)d_in[4];
    const float* g1w0 = (const float*)d_in[5];
    const float* g1b0 = (const float*)d_in[6];
    const float* g2w0 = (const float*)d_in[7];
    const float* g2b0 = (const float*)d_in[8];
    const float* g1w1 = (const float*)d_in[9];
    const float* g1b1 = (const float*)d_in[10];
    const float* g2w1 = (const float*)d_in[11];
    const float* g2b1 = (const float*)d_in[12];

    __half* bufA = (__half*)sym_addr(g_bufA);
    __half* bufB = (__half*)sym_addr(g_bufB);
    __half* w1h  = (__half*)sym_addr(g_w1h);
    __half* w2h  = (__half*)sym_addr(g_w2h);
    __half* l0g1 = (__half*)sym_addr(g_l0g1);
    __half* l0g2 = (__half*)sym_addr(g_l0g2);
    __half* l1g1 = (__half*)sym_addr(g_l1g1);
    __half* l1g2 = (__half*)sym_addr(g_l1g2);

    cudaFuncSetAttribute(gemm_kernel<__half>, cudaFuncAttributeMaxDynamicSharedMemorySize, SMEM_BYTES);
    cudaFuncSetAttribute(gemm_kernel<float>,  cudaFuncAttributeMaxDynamicSharedMemorySize, SMEM_BYTES);

    auto conv = [&](const float* s, __half* d, size_t n) {
        size_t n4 = n / 4;
        unsigned blocks = (unsigned)((n4 + 255) / 256);
        f2h_kernel<<<blocks, 256>>>((const float4*)s, (__half2*)d, n4);
    };

    conv(x,    bufA, (size_t)TOK * HD);
    conv(w1,   w1h,  (size_t)ID * HD);
    conv(w2,   w2h,  (size_t)HD * ID);
    conv(g1w0, l0g1, (size_t)NG * ID * HD);
    conv(g2w0, l0g2, (size_t)NG * HD * ID);
    conv(g1w1, l1g1, (size_t)NG * ID * HD);
    conv(g2w1, l1g2, (size_t)NG * HD * ID);

    dim3 blk(256);
    auto gemm_h = [&](const __half* A, const __half* W, const float* bias, __half* C,
                      int M, int N, int K, int mpg) {
        dim3 grid(N / BN, M / BM);
        gemm_kernel<__half><<<grid, blk, SMEM_BYTES>>>(A, W, bias, C, M, N, K, mpg);
    };

    // stage 1: dense w1  [16384,2048] x [4096,2048]^T -> [16384,4096]
    gemm_h(bufA, w1h, b1, bufB, TOK, ID, HD, TOK);
    // stage 2: dense w2  -> [16384,2048]
    gemm_h(bufB, w2h, b2, bufA, TOK, HD, ID, TOK);
    // layer 0 grouped
    gemm_h(bufA, l0g1, g1b0, bufB, TOK, ID, HD, TOK / NG);
    gemm_h(bufB, l0g2, g2b0, bufA, TOK, HD, ID, TOK / NG);
    // layer 1 grouped
    gemm_h(bufA, l1g1, g1b1, bufB, TOK, ID, HD, TOK / NG);
    // final stage writes fp32 straight to d_out
    {
        dim3 grid(HD / BN, TOK / BM);
        gemm_kernel<float><<<grid, blk, SMEM_BYTES>>>(bufB, l1g2, g2b1, (float*)d_out,
                                                      TOK, HD, ID, TOK / NG);
    }
}